// round 11
// baseline (speedup 1.0000x reference)
#include <cuda_runtime.h>
#include <math.h>

#define DT 0.1f
#define EPS_STAT 0.01f
#define MAXB 131072
#define MAX_EST 16
#define MAX_TOT 64

// scratch (static device memory; no allocations)
__device__ float2 g_cpos[9 * MAXB];   // est-phase (px,py) per step
__device__ float4 g_state[MAXB];      // final est state (px,py,vx,vy)
__device__ float  g_sall[MAX_TOT];    // uniform s per output row

// ---------------- Kernel A: recursion -> compact scratch ----------------
template <int BLOCK>
__global__ void __launch_bounds__(BLOCK)
kalmanA(const float* __restrict__ in,
        const float* __restrict__ sa_p, const float* __restrict__ so_p,
        const float* __restrict__ si_p,
        int B, int n_est, int n_pred) {
    __shared__ float2 gt[MAX_EST];  // (K0, K1) per est step

    const int tid = threadIdx.x;
    const int b = blockIdx.x * BLOCK + tid;

    if (tid == 0) {
        const float sa = *sa_p, so = *so_p, si = *si_p;
        const float g0  = DT * DT * 0.5f;
        const float q00 = sa * sa * (g0 * g0);
        const float q01 = sa * sa * (g0 * DT);
        const float q11 = sa * sa * (DT * DT);
        const float r   = so * so;
        const float eps2 = EPS_STAT * EPS_STAT;
        float P00 = si * si, P01 = 0.0f, P11 = si * si;
        for (int k = 0; k < n_est; k++) {
            float a = P00 + 2.0f * DT * P01 + DT * DT * P11 + q00;
            float c = P01 + DT * P11 + q01;
            float d = P11 + q11;
            P00 = a; P01 = c; P11 = d;
            float S = P00 + r, rs = 1.0f / S;
            float K0 = P00 * rs, K1 = P01 * rs;
            gt[k] = make_float2(K0, K1);
            float omk = 1.0f - K0;
            float A00 = omk * P00;
            float A01 = omk * P01;
            float A10 = P01 - K1 * P00;
            float A11 = P11 - K1 * P01;
            P00 =  A00 * omk      + r * K0 * K0;
            P01 = -A00 * K1 + A01 + r * K0 * K1;
            P11 = -A10 * K1 + A11 + r * K1 * K1;
            if (blockIdx.x == 0) g_sall[k] = sqrtf(fmaxf(P00, eps2));
        }
        if (blockIdx.x == 0) {
            for (int j = 0; j < n_pred; j++) {
                float a = P00 + 2.0f * DT * P01 + DT * DT * P11 + q00;
                float c = P01 + DT * P11 + q01;
                float d = P11 + q11;
                P00 = a; P01 = c; P11 = d;
                g_sall[n_est + j] = sqrtf(fmaxf(P00, eps2));
            }
        }
    }
    __syncthreads();
    if (b >= B) return;

    const float2* __restrict__ zin = reinterpret_cast<const float2*>(in);
    float2 z0 = zin[b];
    float2 z1 = zin[(size_t)B + b];
    float px = z0.x, py = z0.y;
    float vx = (z1.x - z0.x) * (1.0f / DT);
    float vy = (z1.y - z0.y) * (1.0f / DT);
    float2 z = z1;

    for (int t = 0; t < n_est; t++) {
        px += DT * vx;
        py += DT * vy;
        float2 g = gt[t];
        float yx = z.x - px, yy = z.y - py;
        px += g.x * yx; vx += g.y * yx;
        py += g.x * yy; vy += g.y * yy;
        if (t + 1 < n_est) z = zin[(size_t)(t + 2) * B + b];
        g_cpos[t * B + b] = make_float2(px, py);  // coalesced STG.64
    }
    g_state[b] = make_float4(px, py, vx, vy);     // coalesced STG.128
}

// ---------------- Kernel B: expand scratch -> final layout ----------------
// Each thread owns ONE float4 slot of the row pattern and writes it for all
// 39 rows: 39 independent coalesced STG.128, no smem, no sync.
// Row pattern per 4 elements (20 floats = 5 float4):
//   cb0: (p0x,p0y,s, s)  cb1: (0,p1x,p1y,s)  cb2: (s,0,p2x,p2y)
//   cb3: (s, s, 0,p3x)   cb4: (p3y,s,s,0)
template <int BLOCK>
__global__ void __launch_bounds__(BLOCK)
kalmanB(float* __restrict__ out, int B, int n_est, int n_pred) {
    const int f = blockIdx.x * BLOCK + threadIdx.x;  // float4 slot in a row
    const int G4 = (B * 5) >> 2;
    if (f >= G4) return;

    const int cb = f % 5;
    const int e  = 4 * (f / 5) + ((cb < 3) ? cb : 3);

    // per-thread constant masks (computed once)
    float4 pxm, pym, sm;
    switch (cb) {
        case 0: pxm = make_float4(1,0,0,0); pym = make_float4(0,1,0,0); sm = make_float4(0,0,1,1); break;
        case 1: pxm = make_float4(0,1,0,0); pym = make_float4(0,0,1,0); sm = make_float4(0,0,0,1); break;
        case 2: pxm = make_float4(0,0,1,0); pym = make_float4(0,0,0,1); sm = make_float4(1,0,0,0); break;
        case 3: pxm = make_float4(0,0,0,1); pym = make_float4(0,0,0,0); sm = make_float4(1,1,0,0); break;
        default:pxm = make_float4(0,0,0,0); pym = make_float4(1,0,0,0); sm = make_float4(0,1,1,0); break;
    }

    float4 st4 = g_state[e];            // L2-resident
    float4* __restrict__ out4 = reinterpret_cast<float4*>(out) + f;
    const long long stride = G4;

    // est rows: gather compact (px,py)
    for (int t = 0; t < n_est; t++) {
        float2 cp = g_cpos[t * B + e];
        float s = g_sall[t];
        float4 v;
        v.x = fmaf(cp.x, pxm.x, fmaf(cp.y, pym.x, s * sm.x));
        v.y = fmaf(cp.x, pxm.y, fmaf(cp.y, pym.y, s * sm.y));
        v.z = fmaf(cp.x, pxm.z, fmaf(cp.y, pym.z, s * sm.z));
        v.w = fmaf(cp.x, pxm.w, fmaf(cp.y, pym.w, s * sm.w));
        out4[(long long)t * stride] = v;
    }

    // pred rows: incremental closed form
    float qx = st4.x, qy = st4.y;
    const float dx = DT * st4.z, dy = DT * st4.w;
    for (int t = n_est; t < n_est + n_pred; t++) {
        qx += dx; qy += dy;
        float s = g_sall[t];
        float4 v;
        v.x = fmaf(qx, pxm.x, fmaf(qy, pym.x, s * sm.x));
        v.y = fmaf(qx, pxm.y, fmaf(qy, pym.y, s * sm.y));
        v.z = fmaf(qx, pxm.z, fmaf(qy, pym.z, s * sm.z));
        v.w = fmaf(qx, pxm.w, fmaf(qy, pym.w, s * sm.w));
        out4[(long long)t * stride] = v;
    }
}

extern "C" void kernel_launch(void* const* d_in, const int* in_sizes, int n_in,
                              void* d_out, int out_size) {
    const float* inputs  = (const float*)d_in[0];
    const float* sigma_a = (const float*)d_in[1];
    const float* sigma_o = (const float*)d_in[2];
    const float* sigma_i = (const float*)d_in[3];

    const int T_OBS = 10;
    const int B = in_sizes[0] / (T_OBS * 2);
    const int n_est = T_OBS - 1;                // 9
    const int totalSteps = out_size / (B * 5);  // 39
    const int n_pred = totalSteps - n_est;      // 30

    constexpr int BLOCK = 256;
    const int gridA = (B + BLOCK - 1) / BLOCK;
    kalmanA<BLOCK><<<gridA, BLOCK>>>(inputs, sigma_a, sigma_o, sigma_i,
                                     B, n_est, n_pred);

    const int G4 = (B * 5) / 4;
    const int gridB = (G4 + BLOCK - 1) / BLOCK;
    kalmanB<BLOCK><<<gridB, BLOCK>>>((float*)d_out, B, n_est, n_pred);
}

// round 12
// speedup vs baseline: 1.0871x; 1.0871x over previous
#include <cuda_runtime.h>
#include <math.h>

#define DT 0.1f
#define EPS_STAT 0.01f
#define TCH 2  // time chunks

// Fused kernel: each thread owns ONE float4 slot of the 5-float4 row pattern,
// runs the est recursion for its single batch element inline, and writes its
// slot for its chunk's rows. No scratch, no smem staging, no block sync in
// the hot loop. Row pattern per 4 elements (20 floats = 5 float4):
//   cb0:(p0x,p0y,s,s) cb1:(0,p1x,p1y,s) cb2:(s,0,p2x,p2y) cb3:(s,s,0,p3x) cb4:(p3y,s,s,0)
template <int BLOCK>
__global__ void __launch_bounds__(BLOCK, 6)
kalman_kernel(const float* __restrict__ in, float* __restrict__ out,
              const float* __restrict__ sa_p, const float* __restrict__ so_p,
              const float* __restrict__ si_p,
              int B, int n_est, int n_pred) {
    __shared__ float4 gt[16];  // est: (K0, K1, s, 0)
    __shared__ float  st[64];  // pred: s

    const int tid = threadIdx.x;
    const int total = n_est + n_pred;

    // ---- thread 0: uniform covariance recursion -> tables ----
    if (tid == 0) {
        const float sa = *sa_p, so = *so_p, si = *si_p;
        const float g0  = DT * DT * 0.5f;
        const float q00 = sa * sa * (g0 * g0);
        const float q01 = sa * sa * (g0 * DT);
        const float q11 = sa * sa * (DT * DT);
        const float r   = so * so;
        const float eps2 = EPS_STAT * EPS_STAT;
        float P00 = si * si, P01 = 0.0f, P11 = si * si;
        for (int k = 0; k < n_est; k++) {
            float a = P00 + 2.0f * DT * P01 + DT * DT * P11 + q00;
            float c = P01 + DT * P11 + q01;
            float d = P11 + q11;
            P00 = a; P01 = c; P11 = d;
            float S = P00 + r, rs = 1.0f / S;
            float K0 = P00 * rs, K1 = P01 * rs;
            float omk = 1.0f - K0;
            float A00 = omk * P00;
            float A01 = omk * P01;
            float A10 = P01 - K1 * P00;
            float A11 = P11 - K1 * P01;
            P00 =  A00 * omk      + r * K0 * K0;
            P01 = -A00 * K1 + A01 + r * K0 * K1;
            P11 = -A10 * K1 + A11 + r * K1 * K1;
            gt[k] = make_float4(K0, K1, sqrtf(fmaxf(P00, eps2)), 0.0f);
        }
        for (int j = 0; j < n_pred; j++) {
            float a = P00 + 2.0f * DT * P01 + DT * DT * P11 + q00;
            float c = P01 + DT * P11 + q01;
            float d = P11 + q11;
            P00 = a; P01 = c; P11 = d;
            st[j] = sqrtf(fmaxf(P00, eps2));
        }
    }
    __syncthreads();  // only block-wide sync

    const int f  = blockIdx.x * BLOCK + tid;   // float4 slot within a row
    const int G4 = (B * 5) >> 2;
    if (f >= G4) return;

    // chunk-owned output rows [t_lo, t_hi)
    const int chunk = blockIdx.y;
    const int t_lo = (chunk * total) / TCH;
    const int t_hi = ((chunk + 1) * total) / TCH;

    const int cb = f % 5;
    const int e  = 4 * (f / 5) + ((cb < 3) ? cb : 3);  // my batch element

    // per-thread constant masks
    float4 pxm, pym, sm;
    switch (cb) {
        case 0: pxm = make_float4(1,0,0,0); pym = make_float4(0,1,0,0); sm = make_float4(0,0,1,1); break;
        case 1: pxm = make_float4(0,1,0,0); pym = make_float4(0,0,1,0); sm = make_float4(0,0,0,1); break;
        case 2: pxm = make_float4(0,0,1,0); pym = make_float4(0,0,0,1); sm = make_float4(1,0,0,0); break;
        case 3: pxm = make_float4(0,0,0,1); pym = make_float4(0,0,0,0); sm = make_float4(1,1,0,0); break;
        default:pxm = make_float4(0,0,0,0); pym = make_float4(1,0,0,0); sm = make_float4(0,1,1,0); break;
    }

    // ---- init state for my element ----
    const float2* __restrict__ zin = reinterpret_cast<const float2*>(in);
    float2 z0 = zin[e];
    float2 z1 = zin[(size_t)B + e];
    float px = z0.x, py = z0.y;
    float vx = (z1.x - z0.x) * (1.0f / DT);
    float vy = (z1.y - z0.y) * (1.0f / DT);
    float2 z = z1;

    float4* __restrict__ out4 = reinterpret_cast<float4*>(out) + f;
    const long long stride = G4;

    // ---- est recursion (always run; store only owned rows) ----
    for (int t = 0; t < n_est; t++) {
        px += DT * vx;
        py += DT * vy;
        float4 g = gt[t];
        float yx = z.x - px, yy = z.y - py;
        px += g.x * yx; vx += g.y * yx;
        py += g.x * yy; vy += g.y * yy;
        if (t + 1 < n_est) z = zin[(size_t)(t + 2) * B + e];

        if (t >= t_lo && t < t_hi) {
            float s = g.z;
            float4 v;
            v.x = fmaf(px, pxm.x, fmaf(py, pym.x, s * sm.x));
            v.y = fmaf(px, pxm.y, fmaf(py, pym.y, s * sm.y));
            v.z = fmaf(px, pxm.z, fmaf(py, pym.z, s * sm.z));
            v.w = fmaf(px, pxm.w, fmaf(py, pym.w, s * sm.w));
            out4[(long long)t * stride] = v;
        }
    }

    // ---- pred rows in [max(t_lo, n_est), t_hi): closed-form, independent stores ----
    const int p_lo = max(t_lo, n_est);
    float qx = fmaf((float)(p_lo - n_est) * DT, vx, px);
    float qy = fmaf((float)(p_lo - n_est) * DT, vy, py);
    const float dx = DT * vx, dy = DT * vy;
    for (int t = p_lo; t < t_hi; t++) {
        qx += dx; qy += dy;
        float s = st[t - n_est];
        float4 v;
        v.x = fmaf(qx, pxm.x, fmaf(qy, pym.x, s * sm.x));
        v.y = fmaf(qx, pxm.y, fmaf(qy, pym.y, s * sm.y));
        v.z = fmaf(qx, pxm.z, fmaf(qy, pym.z, s * sm.z));
        v.w = fmaf(qx, pxm.w, fmaf(qy, pym.w, s * sm.w));
        out4[(long long)t * stride] = v;
    }
}

extern "C" void kernel_launch(void* const* d_in, const int* in_sizes, int n_in,
                              void* d_out, int out_size) {
    const float* inputs  = (const float*)d_in[0];
    const float* sigma_a = (const float*)d_in[1];
    const float* sigma_o = (const float*)d_in[2];
    const float* sigma_i = (const float*)d_in[3];

    const int T_OBS = 10;
    const int B = in_sizes[0] / (T_OBS * 2);
    const int n_est = T_OBS - 1;                // 9
    const int totalSteps = out_size / (B * 5);  // 39
    const int n_pred = totalSteps - n_est;      // 30

    constexpr int BLOCK = 256;
    const int G4 = (B * 5) / 4;
    dim3 grid((G4 + BLOCK - 1) / BLOCK, TCH);
    kalman_kernel<BLOCK><<<grid, BLOCK>>>(inputs, (float*)d_out,
                                          sigma_a, sigma_o, sigma_i,
                                          B, n_est, n_pred);
}

// round 13
// speedup vs baseline: 1.2449x; 1.1452x over previous
#include <cuda_runtime.h>
#include <math.h>

#define DT 0.1f
#define EPS_STAT 0.01f

// slot-per-thread fused kernel:
//   thread f owns one float4 slot of the 5-float4-per-4-elements row pattern,
//   runs the 9-step est recursion for its single batch element inline
//   (buffering px,py in registers), then emits all 39 rows as one unrolled
//   burst of independent coalesced STG.128. No scratch, no staging smem,
//   no sync in the hot path.
// Row pattern: cb0:(p0x,p0y,s,s) cb1:(0,p1x,p1y,s) cb2:(s,0,p2x,p2y)
//              cb3:(s,s,0,p3x)   cb4:(p3y,s,s,0)
template <int BLOCK, int NEST, int NPRED>
__global__ void __launch_bounds__(BLOCK)
kalman_fused(const float* __restrict__ in, float* __restrict__ out,
             const float* __restrict__ sa_p, const float* __restrict__ so_p,
             const float* __restrict__ si_p, int B) {
    __shared__ float4 gt[NEST];   // (K0, K1, s, 0)
    __shared__ float  st[NPRED];  // s per pred row

    const int tid = threadIdx.x;

    if (tid == 0) {
        const float sa = *sa_p, so = *so_p, si = *si_p;
        const float g0  = DT * DT * 0.5f;
        const float q00 = sa * sa * (g0 * g0);
        const float q01 = sa * sa * (g0 * DT);
        const float q11 = sa * sa * (DT * DT);
        const float r   = so * so;
        const float eps2 = EPS_STAT * EPS_STAT;
        float P00 = si * si, P01 = 0.0f, P11 = si * si;
        #pragma unroll
        for (int k = 0; k < NEST; k++) {
            float a = P00 + 2.0f * DT * P01 + DT * DT * P11 + q00;
            float c = P01 + DT * P11 + q01;
            float d = P11 + q11;
            P00 = a; P01 = c; P11 = d;
            float S = P00 + r, rs = 1.0f / S;
            float K0 = P00 * rs, K1 = P01 * rs;
            float omk = 1.0f - K0;
            float A00 = omk * P00;
            float A01 = omk * P01;
            float A10 = P01 - K1 * P00;
            float A11 = P11 - K1 * P01;
            P00 =  A00 * omk      + r * K0 * K0;
            P01 = -A00 * K1 + A01 + r * K0 * K1;
            P11 = -A10 * K1 + A11 + r * K1 * K1;
            gt[k] = make_float4(K0, K1, sqrtf(fmaxf(P00, eps2)), 0.0f);
        }
        #pragma unroll
        for (int j = 0; j < NPRED; j++) {
            float a = P00 + 2.0f * DT * P01 + DT * DT * P11 + q00;
            float c = P01 + DT * P11 + q01;
            float d = P11 + q11;
            P00 = a; P01 = c; P11 = d;
            st[j] = sqrtf(fmaxf(P00, eps2));
        }
    }
    __syncthreads();

    const int f  = blockIdx.x * BLOCK + tid;
    const int G4 = (B * 5) >> 2;
    if (f >= G4) return;

    const int cb = f % 5;
    const int e  = 4 * (f / 5) + ((cb < 3) ? cb : 3);

    float4 pxm, pym, sm;
    switch (cb) {
        case 0: pxm = make_float4(1,0,0,0); pym = make_float4(0,1,0,0); sm = make_float4(0,0,1,1); break;
        case 1: pxm = make_float4(0,1,0,0); pym = make_float4(0,0,1,0); sm = make_float4(0,0,0,1); break;
        case 2: pxm = make_float4(0,0,1,0); pym = make_float4(0,0,0,1); sm = make_float4(1,0,0,0); break;
        case 3: pxm = make_float4(0,0,0,1); pym = make_float4(0,0,0,0); sm = make_float4(1,1,0,0); break;
        default:pxm = make_float4(0,0,0,0); pym = make_float4(1,0,0,0); sm = make_float4(0,1,1,0); break;
    }

    const float2* __restrict__ zin = reinterpret_cast<const float2*>(in);
    float2 z0 = zin[e];
    float2 z1 = zin[(size_t)B + e];
    float px = z0.x, py = z0.y;
    float vx = (z1.x - z0.x) * (1.0f / DT);
    float vy = (z1.y - z0.y) * (1.0f / DT);
    float2 z = z1;

    // est recursion, buffering positions in registers
    float rpx[NEST], rpy[NEST];
    #pragma unroll
    for (int t = 0; t < NEST; t++) {
        px += DT * vx;
        py += DT * vy;
        float4 g = gt[t];
        float yx = z.x - px, yy = z.y - py;
        px += g.x * yx; vx += g.y * yx;
        py += g.x * yy; vy += g.y * yy;
        if (t + 1 < NEST) z = zin[(size_t)(t + 2) * B + e];
        rpx[t] = px; rpy[t] = py;
    }

    // one unrolled burst of 39 independent coalesced STG.128
    float4* __restrict__ out4 = reinterpret_cast<float4*>(out) + f;
    const long long stride = G4;

    #pragma unroll
    for (int t = 0; t < NEST; t++) {
        const float s = gt[t].z;
        float4 v;
        v.x = fmaf(rpx[t], pxm.x, fmaf(rpy[t], pym.x, s * sm.x));
        v.y = fmaf(rpx[t], pxm.y, fmaf(rpy[t], pym.y, s * sm.y));
        v.z = fmaf(rpx[t], pxm.z, fmaf(rpy[t], pym.z, s * sm.z));
        v.w = fmaf(rpx[t], pxm.w, fmaf(rpy[t], pym.w, s * sm.w));
        out4[(long long)t * stride] = v;
    }

    float qx = px, qy = py;
    const float dx = DT * vx, dy = DT * vy;
    #pragma unroll
    for (int j = 0; j < NPRED; j++) {
        qx += dx; qy += dy;
        const float s = st[j];
        float4 v;
        v.x = fmaf(qx, pxm.x, fmaf(qy, pym.x, s * sm.x));
        v.y = fmaf(qx, pxm.y, fmaf(qy, pym.y, s * sm.y));
        v.z = fmaf(qx, pxm.z, fmaf(qy, pym.z, s * sm.z));
        v.w = fmaf(qx, pxm.w, fmaf(qy, pym.w, s * sm.w));
        out4[(long long)(NEST + j) * stride] = v;
    }
}

// generic fallback (any shapes / alignment): simple per-element scalar kernel
__global__ void kalman_generic(const float* __restrict__ in, float* __restrict__ out,
                               const float* __restrict__ sa_p, const float* __restrict__ so_p,
                               const float* __restrict__ si_p,
                               int B, int n_est, int n_pred) {
    const int b = blockIdx.x * blockDim.x + threadIdx.x;
    if (b >= B) return;
    const float sa = *sa_p, so = *so_p, si = *si_p;
    const float g0  = DT * DT * 0.5f;
    const float q00 = sa * sa * (g0 * g0);
    const float q01 = sa * sa * (g0 * DT);
    const float q11 = sa * sa * (DT * DT);
    const float r   = so * so;
    const float eps2 = EPS_STAT * EPS_STAT;
    float P00 = si * si, P01 = 0.0f, P11 = si * si;
    const float2* zin = reinterpret_cast<const float2*>(in);
    float2 z0 = zin[b], z1 = zin[(size_t)B + b];
    float px = z0.x, py = z0.y;
    float vx = (z1.x - z0.x) / DT, vy = (z1.y - z0.y) / DT;
    for (int t = 0; t < n_est + n_pred; t++) {
        float a = P00 + 2.0f * DT * P01 + DT * DT * P11 + q00;
        float c = P01 + DT * P11 + q01;
        float d = P11 + q11;
        P00 = a; P01 = c; P11 = d;
        px += DT * vx; py += DT * vy;
        if (t < n_est) {
            float2 z = zin[(size_t)(t + 1) * B + b];
            float S = P00 + r, rs = 1.0f / S;
            float K0 = P00 * rs, K1 = P01 * rs;
            float yx = z.x - px, yy = z.y - py;
            px += K0 * yx; vx += K1 * yx;
            py += K0 * yy; vy += K1 * yy;
            float omk = 1.0f - K0;
            float A00 = omk * P00, A01 = omk * P01;
            float A10 = P01 - K1 * P00, A11 = P11 - K1 * P01;
            P00 =  A00 * omk      + r * K0 * K0;
            P01 = -A00 * K1 + A01 + r * K0 * K1;
            P11 = -A10 * K1 + A11 + r * K1 * K1;
        }
        float s = sqrtf(fmaxf(P00, eps2));
        float* dptr = out + (long long)t * B * 5 + (long long)b * 5;
        dptr[0] = px; dptr[1] = py; dptr[2] = s; dptr[3] = s; dptr[4] = 0.0f;
    }
}

extern "C" void kernel_launch(void* const* d_in, const int* in_sizes, int n_in,
                              void* d_out, int out_size) {
    const float* inputs  = (const float*)d_in[0];
    const float* sigma_a = (const float*)d_in[1];
    const float* sigma_o = (const float*)d_in[2];
    const float* sigma_i = (const float*)d_in[3];

    const int T_OBS = 10;
    const int B = in_sizes[0] / (T_OBS * 2);
    const int n_est = T_OBS - 1;                // 9
    const int totalSteps = out_size / (B * 5);  // 39
    const int n_pred = totalSteps - n_est;      // 30

    if (n_est == 9 && n_pred == 30 && (B % 4) == 0) {
        constexpr int BLOCK = 128;
        const int G4 = (B * 5) / 4;
        const int grid = (G4 + BLOCK - 1) / BLOCK;
        kalman_fused<BLOCK, 9, 30><<<grid, BLOCK>>>(
            inputs, (float*)d_out, sigma_a, sigma_o, sigma_i, B);
    } else {
        const int grid = (B + 255) / 256;
        kalman_generic<<<grid, 256>>>(inputs, (float*)d_out,
                                      sigma_a, sigma_o, sigma_i,
                                      B, n_est, n_pred);
    }
}